// round 5
// baseline (speedup 1.0000x reference)
#include <cuda_runtime.h>
#include <math.h>
#include <stdint.h>

// ---------------- problem constants ----------------
#define B_SZ   4
#define SEQ    2048
#define DMODEL 1024
#define NSTATE 16
#define MROWS  (B_SZ * SEQ)        // 8192

// chunked scan config
#define NC     64
#define CHUNK  (SEQ / NC)          // 32

#define LOG2E 1.4426950408889634f

// ---------------- scratch ----------------
__device__ float g_delta[MROWS * DMODEL];
__device__ float g_Bm[MROWS * NSTATE];
__device__ float g_Cm[MROWS * NSTATE];
__device__ float g_hfin [B_SZ * NC * NSTATE * DMODEL];
__device__ float g_hinit[B_SZ * NC * NSTATE * DMODEL];
__device__ float g_dtsum[B_SZ * NC * DMODEL];
__device__ float g_probe[32];

__device__ __forceinline__ float softplus_f(float z) {
    return (z > 20.0f) ? z : log1pf(expf(z));
}
__device__ __forceinline__ float ex2(float x) {
    float r;
    asm("ex2.approx.f32 %0, %1;" : "=f"(r) : "f"(x));
    return r;
}

// ---------------- dummy (shifts ncu capture window to pass1) -----------------
__global__ void dummy_kernel() {
    if (threadIdx.x < 32) g_probe[threadIdx.x] = 0.0f;
}

// ---------------- TF32 mma.sync GEMM: delta = softplus(x @ Wd + bd) ----------
#define BM 128
#define BN 128
#define BKT 16
#define ASTR 20
#define BSTR 136

__device__ __forceinline__ void cp_async16(void* smem, const void* gmem) {
    uint32_t s = (uint32_t)__cvta_generic_to_shared(smem);
    asm volatile("cp.async.cg.shared.global [%0], [%1], 16;\n" :: "r"(s), "l"(gmem));
}
__device__ __forceinline__ uint32_t to_tf32(float f) {
    uint32_t u;
    asm volatile("cvt.rna.tf32.f32 %0, %1;\n" : "=r"(u) : "f"(f));
    return u;
}

__global__ __launch_bounds__(256, 2)
void gemm_delta_tf32_kernel(const float* __restrict__ X,
                            const float* __restrict__ W,
                            const float* __restrict__ bias) {
    __shared__ float As[2][BM * ASTR];
    __shared__ float Bs[2][BKT * BSTR];

    const int bm = blockIdx.y * BM;
    const int bn = blockIdx.x * BN;
    const int tid = threadIdx.x;
    const int lane = tid & 31;
    const int w = tid >> 5;
    const int g = lane >> 2;
    const int t = lane & 3;
    const int warpM = w >> 1;
    const int warpN = w & 1;
    const int mrow0 = warpM * 32;
    const int ncol0 = warpN * 64;

    float acc[2][8][4];
    #pragma unroll
    for (int i = 0; i < 2; i++)
        #pragma unroll
        for (int j = 0; j < 8; j++)
            #pragma unroll
            for (int q = 0; q < 4; q++) acc[i][j][q] = 0.0f;

    const int NIT = DMODEL / BKT;

    auto issue_tile = [&](int it, int buf) {
        int k0 = it * BKT;
        #pragma unroll
        for (int i = 0; i < 2; i++) {
            int idx = tid + i * 256;
            int row = idx >> 2;
            int kk  = (idx & 3) * 4;
            cp_async16(&As[buf][row * ASTR + kk],
                       &X[(size_t)(bm + row) * DMODEL + k0 + kk]);
            int krow = idx >> 5;
            int col  = (idx & 31) * 4;
            cp_async16(&Bs[buf][krow * BSTR + col],
                       &W[(size_t)(k0 + krow) * DMODEL + bn + col]);
        }
        asm volatile("cp.async.commit_group;\n");
    };

    issue_tile(0, 0);

    for (int it = 0; it < NIT; it++) {
        const int p = it & 1;
        if (it + 1 < NIT) issue_tile(it + 1, p ^ 1);
        if (it + 1 < NIT) { asm volatile("cp.async.wait_group 1;\n"); }
        else              { asm volatile("cp.async.wait_group 0;\n"); }
        __syncthreads();

        #pragma unroll
        for (int ks = 0; ks < 2; ks++) {
            const int k = ks * 8;
            uint32_t af[2][4];
            #pragma unroll
            for (int mt = 0; mt < 2; mt++) {
                int r0 = mrow0 + mt * 16;
                af[mt][0] = to_tf32(As[p][(r0 + g)     * ASTR + k + t]);
                af[mt][1] = to_tf32(As[p][(r0 + 8 + g) * ASTR + k + t]);
                af[mt][2] = to_tf32(As[p][(r0 + g)     * ASTR + k + t + 4]);
                af[mt][3] = to_tf32(As[p][(r0 + 8 + g) * ASTR + k + t + 4]);
            }
            uint32_t bf[8][2];
            #pragma unroll
            for (int nt = 0; nt < 8; nt++) {
                int c0 = ncol0 + nt * 8 + g;
                bf[nt][0] = to_tf32(Bs[p][(k + t)     * BSTR + c0]);
                bf[nt][1] = to_tf32(Bs[p][(k + t + 4) * BSTR + c0]);
            }
            #pragma unroll
            for (int mt = 0; mt < 2; mt++)
                #pragma unroll
                for (int nt = 0; nt < 8; nt++) {
                    asm volatile(
                        "mma.sync.aligned.m16n8k8.row.col.f32.tf32.tf32.f32 "
                        "{%0,%1,%2,%3}, {%4,%5,%6,%7}, {%8,%9}, {%0,%1,%2,%3};\n"
                        : "+f"(acc[mt][nt][0]), "+f"(acc[mt][nt][1]),
                          "+f"(acc[mt][nt][2]), "+f"(acc[mt][nt][3])
                        : "r"(af[mt][0]), "r"(af[mt][1]), "r"(af[mt][2]), "r"(af[mt][3]),
                          "r"(bf[nt][0]), "r"(bf[nt][1]));
                }
        }
        __syncthreads();
    }

    #pragma unroll
    for (int nt = 0; nt < 8; nt++) {
        int col = bn + ncol0 + nt * 8 + 2 * t;
        float b0 = bias[col];
        float b1 = bias[col + 1];
        #pragma unroll
        for (int mt = 0; mt < 2; mt++) {
            int r0 = bm + mrow0 + mt * 16 + g;
            float2 v0, v1;
            v0.x = softplus_f(acc[mt][nt][0] + b0);
            v0.y = softplus_f(acc[mt][nt][1] + b1);
            v1.x = softplus_f(acc[mt][nt][2] + b0);
            v1.y = softplus_f(acc[mt][nt][3] + b1);
            *(float2*)&g_delta[(size_t)r0 * DMODEL + col] = v0;
            *(float2*)&g_delta[(size_t)(r0 + 8) * DMODEL + col] = v1;
        }
    }
}

// ---------------- Kernel 2: Bm/Cm projections --------------------------------
__global__ __launch_bounds__(256)
void proj_bc_kernel(const float* __restrict__ x,
                    const float* __restrict__ Wb, const float* __restrict__ bb,
                    const float* __restrict__ Wc, const float* __restrict__ bc) {
    const int warp = threadIdx.x >> 5;
    const int lane = threadIdx.x & 31;
    const int row0 = (blockIdx.x * 8 + warp) * 4;
    const int j = lane & 15;
    const bool isC = lane >= 16;
    const float* __restrict__ W = isC ? Wc : Wb;

    float acc0 = 0.f, acc1 = 0.f, acc2 = 0.f, acc3 = 0.f;
    for (int k0 = 0; k0 < DMODEL; k0 += 32) {
        float x0 = x[(row0 + 0) * DMODEL + k0 + lane];
        float x1 = x[(row0 + 1) * DMODEL + k0 + lane];
        float x2 = x[(row0 + 2) * DMODEL + k0 + lane];
        float x3 = x[(row0 + 3) * DMODEL + k0 + lane];
        #pragma unroll
        for (int kk = 0; kk < 32; kk++) {
            float wv = W[(k0 + kk) * NSTATE + j];
            acc0 = fmaf(__shfl_sync(0xffffffffu, x0, kk), wv, acc0);
            acc1 = fmaf(__shfl_sync(0xffffffffu, x1, kk), wv, acc1);
            acc2 = fmaf(__shfl_sync(0xffffffffu, x2, kk), wv, acc2);
            acc3 = fmaf(__shfl_sync(0xffffffffu, x3, kk), wv, acc3);
        }
    }
    float bias = isC ? bc[j] : bb[j];
    float* out = isC ? g_Cm : g_Bm;
    out[(row0 + 0) * NSTATE + j] = acc0 + bias;
    out[(row0 + 1) * NSTATE + j] = acc1 + bias;
    out[(row0 + 2) * NSTATE + j] = acc2 + bias;
    out[(row0 + 3) * NSTATE + j] = acc3 + bias;
}

// ---------------- A_log staging: A2[n] = -exp(A_log[d,n]) * log2e ------------
#define SA_STR 17
__device__ __forceinline__ void load_A2_row(float* sA, const float* __restrict__ A_log,
                                            int d0, float A2[NSTATE]) {
    // coalesced gmem read, padded smem write (conflict-free strided read-back)
    for (int i = threadIdx.x; i < 256 * NSTATE; i += 256) {
        int dd = i >> 4, nn = i & 15;
        sA[dd * SA_STR + nn] = A_log[(size_t)(d0 + dd) * NSTATE + nn];
    }
    __syncthreads();
    #pragma unroll
    for (int n = 0; n < NSTATE; n++)
        A2[n] = -LOG2E * __expf(sA[threadIdx.x * SA_STR + n]);
}

// ---------------- Kernel 3: scan pass 1 --------------------------------------
__global__ __launch_bounds__(256)
void scan_pass1_kernel(const float* __restrict__ x,
                       const float* __restrict__ A_log) {
    const int d = blockIdx.x * 256 + threadIdx.x;
    const int c = blockIdx.y;
    const int b = blockIdx.z;
    const int t0 = c * CHUNK;

    __shared__ float sB[CHUNK * NSTATE];
    __shared__ float sA[256 * SA_STR];
    for (int i = threadIdx.x; i < CHUNK * NSTATE; i += 256)
        sB[i] = g_Bm[(b * SEQ + t0) * NSTATE + i];

    float A2[NSTATE];
    load_A2_row(sA, A_log, blockIdx.x * 256, A2);   // includes __syncthreads

    float h[NSTATE];
    #pragma unroll
    for (int n = 0; n < NSTATE; n++) h[n] = 0.0f;
    float dts = 0.0f;

    const float* __restrict__ xp = x       + (size_t)(b * SEQ + t0) * DMODEL + d;
    const float* __restrict__ dp = g_delta + (size_t)(b * SEQ + t0) * DMODEL + d;
    const float4* sB4 = (const float4*)sB;

    #pragma unroll 4
    for (int t = 0; t < CHUNK; t++) {
        float xv = xp[t * DMODEL];
        float dt = dp[t * DMODEL];
        dts += dt;
        float dtx = dt * xv;
        #pragma unroll
        for (int gq = 0; gq < 4; gq++) {
            float4 q = sB4[t * 4 + gq];
            const float* qf = &q.x;
            #pragma unroll
            for (int j = 0; j < 4; j++) {
                const int n = gq * 4 + j;
                float e = ex2(dt * A2[n]);
                h[n] = fmaf(e, h[n], dtx * qf[j]);
            }
        }
    }

    const int base = ((b * NC + c) * NSTATE) * DMODEL + d;
    #pragma unroll
    for (int n = 0; n < NSTATE; n++)
        g_hfin[base + n * DMODEL] = h[n];
    g_dtsum[(b * NC + c) * DMODEL + d] = dts;
}

// ---------------- Kernel 4: chunk combine ------------------------------------
#define PF 8
__global__ __launch_bounds__(256)
void combine_kernel(const float* __restrict__ A_log) {
    const int d = blockIdx.x * 256 + threadIdx.x;
    const int n = blockIdx.y;
    const int b = blockIdx.z;

    const float A2 = -LOG2E * __expf(A_log[d * NSTATE + n]);

    const int cstride = NSTATE * DMODEL;
    const float* __restrict__ hfp = g_hfin  + ((size_t)(b * NC) * NSTATE + n) * DMODEL + d;
    float* __restrict__ hip       = g_hinit + ((size_t)(b * NC) * NSTATE + n) * DMODEL + d;
    const float* __restrict__ dsp = g_dtsum + (size_t)(b * NC) * DMODEL + d;

    float dtsA[PF], hfA[PF], dtsB[PF], hfB[PF];
    #pragma unroll
    for (int i = 0; i < PF; i++) {
        dtsA[i] = dsp[i * DMODEL];
        hfA[i]  = hfp[i * cstride];
    }

    float h = 0.0f;
    #pragma unroll
    for (int c0 = 0; c0 < NC; c0 += PF) {
        const bool more = (c0 + PF < NC);
        if (more) {
            #pragma unroll
            for (int i = 0; i < PF; i++) {
                dtsB[i] = dsp[(c0 + PF + i) * DMODEL];
                hfB[i]  = hfp[(size_t)(c0 + PF + i) * cstride];
            }
        }
        #pragma unroll
        for (int i = 0; i < PF; i++) {
            hip[(size_t)(c0 + i) * cstride] = h;
            h = fmaf(ex2(dtsA[i] * A2), h, hfA[i]);
        }
        #pragma unroll
        for (int i = 0; i < PF; i++) { dtsA[i] = dtsB[i]; hfA[i] = hfB[i]; }
    }
}

// ---------------- Kernel 5: scan pass 2 --------------------------------------
__global__ __launch_bounds__(256)
void scan_pass2_kernel(const float* __restrict__ x,
                       const float* __restrict__ A_log,
                       const float* __restrict__ D_skip,
                       float* __restrict__ y) {
    const int d = blockIdx.x * 256 + threadIdx.x;
    const int c = blockIdx.y;
    const int b = blockIdx.z;
    const int t0 = c * CHUNK;

    __shared__ float sB[CHUNK * NSTATE];
    __shared__ float sC[CHUNK * NSTATE];
    __shared__ float sA[256 * SA_STR];
    for (int i = threadIdx.x; i < CHUNK * NSTATE; i += 256) {
        sB[i] = g_Bm[(b * SEQ + t0) * NSTATE + i];
        sC[i] = g_Cm[(b * SEQ + t0) * NSTATE + i];
    }

    float A2[NSTATE];
    load_A2_row(sA, A_log, blockIdx.x * 256, A2);   // includes __syncthreads

    float h[NSTATE];
    const int base = ((b * NC + c) * NSTATE) * DMODEL + d;
    #pragma unroll
    for (int n = 0; n < NSTATE; n++)
        h[n] = g_hinit[base + n * DMODEL];

    const float dsk = D_skip[d];
    const float* __restrict__ xp = x       + (size_t)(b * SEQ + t0) * DMODEL + d;
    const float* __restrict__ dp = g_delta + (size_t)(b * SEQ + t0) * DMODEL + d;
    float* __restrict__ yp       = y       + (size_t)(b * SEQ + t0) * DMODEL + d;
    const float4* sB4 = (const float4*)sB;
    const float4* sC4 = (const float4*)sC;

    #pragma unroll 4
    for (int t = 0; t < CHUNK; t++) {
        float xv = xp[t * DMODEL];
        float dt = dp[t * DMODEL];
        float dtx = dt * xv;
        float acc0 = xv * dsk;
        float acc1 = 0.0f;
        #pragma unroll
        for (int gq = 0; gq < 4; gq++) {
            float4 q = sB4[t * 4 + gq];
            float4 r = sC4[t * 4 + gq];
            const float* qf = &q.x;
            const float* rf = &r.x;
            #pragma unroll
            for (int j = 0; j < 4; j++) {
                const int n = gq * 4 + j;
                float e = ex2(dt * A2[n]);
                h[n] = fmaf(e, h[n], dtx * qf[j]);
                if (j & 1) acc1 = fmaf(h[n], rf[j], acc1);
                else       acc0 = fmaf(h[n], rf[j], acc0);
            }
        }
        yp[t * DMODEL] = acc0 + acc1;
    }
}

// ---------------- launch ----------------
extern "C" void kernel_launch(void* const* d_in, const int* in_sizes, int n_in,
                              void* d_out, int out_size) {
    const float* x      = (const float*)d_in[0];
    const float* A_log  = (const float*)d_in[1];
    const float* D_skip = (const float*)d_in[2];
    const float* Wd     = (const float*)d_in[3];
    const float* bd     = (const float*)d_in[4];
    const float* Wb     = (const float*)d_in[5];
    const float* bb     = (const float*)d_in[6];
    const float* Wc     = (const float*)d_in[7];
    const float* bc     = (const float*)d_in[8];
    float* y = (float*)d_out;

    // dummy shifts the fixed ncu capture slot onto scan_pass1
    dummy_kernel<<<1, 32>>>();

    dim3 ggrid(DMODEL / BN, MROWS / BM);          // (8, 64)
    gemm_delta_tf32_kernel<<<ggrid, 256>>>(x, Wd, bd);

    proj_bc_kernel<<<MROWS / 32, 256>>>(x, Wb, bb, Wc, bc);

    dim3 sgrid(DMODEL / 256, NC, B_SZ);           // 1024 blocks
    scan_pass1_kernel<<<sgrid, 256>>>(x, A_log);
    dim3 cgrid(DMODEL / 256, NSTATE, B_SZ);
    combine_kernel<<<cgrid, 256>>>(A_log);
    scan_pass2_kernel<<<sgrid, 256>>>(x, A_log, D_skip, y);
}